// round 9
// baseline (speedup 1.0000x reference)
#include <cuda_runtime.h>
#include <cstdint>

#define NUM_T 15

// Branchless 4-level binary search + LUT lookup, all in one asm block.
// c = #{i : x >= t_i}; returns L[c]. Tables in shared memory at tsh
// (t at +0, L at +64). Conflict-free: both tables < 128B.
__device__ __forceinline__ float bucket(float x, float t7, float t11, float t3,
                                        unsigned tsh)
{
    float y;
    asm volatile(
        "{\n\t"
        ".reg .pred p;\n\t"
        ".reg .f32 tv;\n\t"
        ".reg .u32 off;\n\t"
        "setp.ge.f32 p, %1, %2;\n\t"      // level 1: x >= t[7] ?
        "selp.f32 tv, %3, %4, p;\n\t"     // pivot2 = p ? t[11] : t[3]
        "selp.u32 off, 32, 0, p;\n\t"     // idx bytes: 8*4 or 0
        "setp.ge.f32 p, %1, tv;\n\t"      // level 2
        "@p add.u32 off, off, 16;\n\t"    // += 4*4
        "add.u32 off, off, %5;\n\t"       // off = tsh + 4*idx4
        "ld.shared.f32 tv, [off+4];\n\t"  // t[idx4+1]
        "setp.ge.f32 p, %1, tv;\n\t"      // level 3
        "@p add.u32 off, off, 8;\n\t"     // += 2*4
        "ld.shared.f32 tv, [off];\n\t"    // t[idx2]
        "setp.ge.f32 p, %1, tv;\n\t"      // level 4
        "@p add.u32 off, off, 4;\n\t"     // off = tsh + 4*c
        "ld.shared.f32 %0, [off+64];\n\t" // L[c]
        "}\n\t"
        : "=f"(y)
        : "f"(x), "f"(t7), "f"(t11), "f"(t3), "r"(tsh));
    return y;
}

__device__ __forceinline__ void quad_bucket(float4& r, const float4& v,
                                            float t7, float t11, float t3,
                                            unsigned tsh)
{
    r.x = bucket(v.x, t7, t11, t3, tsh);
    r.y = bucket(v.y, t7, t11, t3, tsh);
    r.z = bucket(v.z, t7, t11, t3, tsh);
    r.w = bucket(v.w, t7, t11, t3, tsh);
}

// Single-launch kernel: each CTA builds the 32-float LUT in smem from the
// raw params (order-preserving, bit-exact), then does the binary-search
// quantize. 4 front-batched streaming LDG.128 per thread (MLP=4); x/y use
// evict-first (.cs) since every line is touched exactly once.
__global__ __launch_bounds__(256)
void kq_kernel_full(const float4* __restrict__ x,
                    float4* __restrict__ y,
                    const float* __restrict__ th,
                    const float* __restrict__ al,
                    const float* __restrict__ bp)
{
    __shared__ float s[32];

    const unsigned nthreads = gridDim.x * blockDim.x;
    const unsigned tid = blockIdx.x * blockDim.x + threadIdx.x;

    // Front-batched streaming loads (independent of smem -> issue first).
    float4 v0 = __ldcs(x + tid);
    float4 v1 = __ldcs(x + tid + nthreads);
    float4 v2 = __ldcs(x + tid + 2u * nthreads);
    float4 v3 = __ldcs(x + tid + 3u * nthreads);

    // Build table: s[0..14] = thresholds, s[15] = pad,
    // s[16+k] = L[k] = b + sum_{j<k} alpha_j (left-assoc = reference order).
    if (threadIdx.x < 32) {
        int i = threadIdx.x;
        float val;
        if (i < 16) {
            val = (i < NUM_T) ? __ldg(th + i) : 0.0f;
        } else {
            int k = i - 16;
            float L = __ldg(bp);
#pragma unroll
            for (int j = 0; j < NUM_T; j++) {
                float aj = __ldg(al + j);
                if (j < k) L += aj;   // predicated, order-preserving
            }
            val = L;
        }
        s[i] = val;
    }
    __syncthreads();

    const unsigned tsh = (unsigned)__cvta_generic_to_shared(s);
    const float t7 = s[7], t11 = s[11], t3 = s[3];

    float4 r0, r1, r2, r3;
    quad_bucket(r0, v0, t7, t11, t3, tsh);
    quad_bucket(r1, v1, t7, t11, t3, tsh);
    quad_bucket(r2, v2, t7, t11, t3, tsh);
    quad_bucket(r3, v3, t7, t11, t3, tsh);

    __stcs(y + tid, r0);
    __stcs(y + tid + nthreads, r1);
    __stcs(y + tid + 2u * nthreads, r2);
    __stcs(y + tid + 3u * nthreads, r3);
}

// Generic fallback (bounds-checked, scalar) — independent of the LUT.
__global__ void kq_tail(const float* __restrict__ x,
                        float* __restrict__ y,
                        const float* __restrict__ th,
                        const float* __restrict__ al,
                        const float* __restrict__ bp,
                        long long start, long long n)
{
    long long i = start + (long long)blockIdx.x * blockDim.x + threadIdx.x;
    if (i >= n) return;
    float v = x[i];
    float r = __ldg(bp);
#pragma unroll
    for (int k = 0; k < NUM_T; k++) {
        asm("{\n\t"
            ".reg .pred p;\n\t"
            "setp.ge.f32 p, %1, %2;\n\t"
            "@p add.f32 %0, %0, %3;\n\t"
            "}"
            : "+f"(r) : "f"(v), "f"(__ldg(th + k)), "f"(__ldg(al + k)));
    }
    y[i] = r;
}

extern "C" void kernel_launch(void* const* d_in, const int* in_sizes, int n_in,
                              void* d_out, int out_size)
{
    // Input order per setup_inputs: x, T, thresholds, alphas, b
    const float* x  = (const float*)d_in[0];
    // d_in[1] = T (backward-only, unused in forward)
    const float* th = (const float*)d_in[2];
    const float* al = (const float*)d_in[3];
    const float* bp = (const float*)d_in[4];
    float* y = (float*)d_out;

    const long long n = (long long)in_sizes[0];
    const int threads = 256;
    const long long per_block = (long long)threads * 4;  // float4s per block
    const long long n4 = n / 4;

    const long long full_blocks = n4 / per_block;
    const long long covered = full_blocks * per_block * 4;  // elements covered

    if (full_blocks > 0) {
        kq_kernel_full<<<(unsigned)full_blocks, threads>>>(
            (const float4*)x, (float4*)y, th, al, bp);
    }
    if (covered < n) {
        long long rem = n - covered;
        int tb = (int)((rem + 255) / 256);
        kq_tail<<<tb, 256>>>(x, y, th, al, bp, covered, n);
    }
}

// round 10
// speedup vs baseline: 1.0035x; 1.0035x over previous
#include <cuda_runtime.h>
#include <cstdint>

#define NUM_T 15

// Branchless 4-level binary search + LUT lookup, all in one asm block.
// c = #{i : x >= t_i}; returns L[c]. Tables in shared memory at tsh
// (t at +0, L at +64). Conflict-free: both tables < 128B.
__device__ __forceinline__ float bucket(float x, float t7, float t11, float t3,
                                        unsigned tsh)
{
    float y;
    asm volatile(
        "{\n\t"
        ".reg .pred p;\n\t"
        ".reg .f32 tv;\n\t"
        ".reg .u32 off;\n\t"
        "setp.ge.f32 p, %1, %2;\n\t"      // level 1: x >= t[7] ?
        "selp.f32 tv, %3, %4, p;\n\t"     // pivot2 = p ? t[11] : t[3]
        "selp.u32 off, 32, 0, p;\n\t"     // idx bytes: 8*4 or 0
        "setp.ge.f32 p, %1, tv;\n\t"      // level 2
        "@p add.u32 off, off, 16;\n\t"    // += 4*4
        "add.u32 off, off, %5;\n\t"       // off = tsh + 4*idx4
        "ld.shared.f32 tv, [off+4];\n\t"  // t[idx4+1]
        "setp.ge.f32 p, %1, tv;\n\t"      // level 3
        "@p add.u32 off, off, 8;\n\t"     // += 2*4
        "ld.shared.f32 tv, [off];\n\t"    // t[idx2]
        "setp.ge.f32 p, %1, tv;\n\t"      // level 4
        "@p add.u32 off, off, 4;\n\t"     // off = tsh + 4*c
        "ld.shared.f32 %0, [off+64];\n\t" // L[c]
        "}\n\t"
        : "=f"(y)
        : "f"(x), "f"(t7), "f"(t11), "f"(t3), "r"(tsh));
    return y;
}

__device__ __forceinline__ void quad_bucket(float4& r, const float4& v,
                                            float t7, float t11, float t3,
                                            unsigned tsh)
{
    r.x = bucket(v.x, t7, t11, t3, tsh);
    r.y = bucket(v.y, t7, t11, t3, tsh);
    r.z = bucket(v.z, t7, t11, t3, tsh);
    r.w = bucket(v.w, t7, t11, t3, tsh);
}

// Single-launch kernel (R8 config: MLP=2, plain loads) with 512-thread
// blocks (halves redundant per-CTA LUT-build traffic) and evict-first
// stores (output lines never re-read).
__global__ __launch_bounds__(512)
void kq_kernel_full(const float4* __restrict__ x,
                    float4* __restrict__ y,
                    const float* __restrict__ th,
                    const float* __restrict__ al,
                    const float* __restrict__ bp)
{
    __shared__ float s[32];

    const unsigned nthreads = gridDim.x * blockDim.x;
    const unsigned tid = blockIdx.x * blockDim.x + threadIdx.x;

    // Front-batched loads (independent of smem -> issue first).
    float4 v0 = x[tid];
    float4 v1 = x[tid + nthreads];

    // Build table: s[0..14] = thresholds, s[15] = pad,
    // s[16+k] = L[k] = b + sum_{j<k} alpha_j (left-assoc = reference order).
    if (threadIdx.x < 32) {
        int i = threadIdx.x;
        float val;
        if (i < 16) {
            val = (i < NUM_T) ? __ldg(th + i) : 0.0f;
        } else {
            int k = i - 16;
            float L = __ldg(bp);
#pragma unroll
            for (int j = 0; j < NUM_T; j++) {
                float aj = __ldg(al + j);
                if (j < k) L += aj;   // predicated, order-preserving
            }
            val = L;
        }
        s[i] = val;
    }
    __syncthreads();

    const unsigned tsh = (unsigned)__cvta_generic_to_shared(s);
    const float t7 = s[7], t11 = s[11], t3 = s[3];

    float4 r0, r1;
    quad_bucket(r0, v0, t7, t11, t3, tsh);
    quad_bucket(r1, v1, t7, t11, t3, tsh);

    __stcs(y + tid, r0);
    __stcs(y + tid + nthreads, r1);
}

// Generic fallback (bounds-checked, scalar) — independent of the LUT.
__global__ void kq_tail(const float* __restrict__ x,
                        float* __restrict__ y,
                        const float* __restrict__ th,
                        const float* __restrict__ al,
                        const float* __restrict__ bp,
                        long long start, long long n)
{
    long long i = start + (long long)blockIdx.x * blockDim.x + threadIdx.x;
    if (i >= n) return;
    float v = x[i];
    float r = __ldg(bp);
#pragma unroll
    for (int k = 0; k < NUM_T; k++) {
        asm("{\n\t"
            ".reg .pred p;\n\t"
            "setp.ge.f32 p, %1, %2;\n\t"
            "@p add.f32 %0, %0, %3;\n\t"
            "}"
            : "+f"(r) : "f"(v), "f"(__ldg(th + k)), "f"(__ldg(al + k)));
    }
    y[i] = r;
}

extern "C" void kernel_launch(void* const* d_in, const int* in_sizes, int n_in,
                              void* d_out, int out_size)
{
    // Input order per setup_inputs: x, T, thresholds, alphas, b
    const float* x  = (const float*)d_in[0];
    // d_in[1] = T (backward-only, unused in forward)
    const float* th = (const float*)d_in[2];
    const float* al = (const float*)d_in[3];
    const float* bp = (const float*)d_in[4];
    float* y = (float*)d_out;

    const long long n = (long long)in_sizes[0];
    const int threads = 512;
    const long long per_block = (long long)threads * 2;  // float4s per block
    const long long n4 = n / 4;

    const long long full_blocks = n4 / per_block;
    const long long covered = full_blocks * per_block * 4;  // elements covered

    if (full_blocks > 0) {
        kq_kernel_full<<<(unsigned)full_blocks, threads>>>(
            (const float4*)x, (float4*)y, th, al, bp);
    }
    if (covered < n) {
        long long rem = n - covered;
        int tb = (int)((rem + 255) / 256);
        kq_tail<<<tb, 256>>>(x, y, th, al, bp, covered, n);
    }
}